// round 1
// baseline (speedup 1.0000x reference)
#include <cuda_runtime.h>
#include <cstddef>

// Problem constants (fixed by the reference setup)
#define B_   4
#define C_   192
#define H_   128
#define W_   128
#define P_   (H_*W_)          // 16384
#define ND   3                // dilations 1,2,3
#define C2   64               // C / ND
#define NH   2                // heads per dilation (C2 / HD)
#define HD   32               // head dim
#define MQKV 576              // 3*C

#define SCALE 0.17677669529663687f   // 32^-0.5

// Scratch (alloc-free: __device__ globals)
__device__ float g_x  [(size_t)B_*C_*P_];     // x + pos_embed + bias   (50 MB)
__device__ float g_qkv[(size_t)B_*MQKV*P_];   // qkv activations       (151 MB)
__device__ float g_xo [(size_t)B_*C_*P_];     // attention output       (50 MB)

// ---------------------------------------------------------------------------
// Stage 1: depthwise 3x3 conv (zero pad) + residual + bias
// ---------------------------------------------------------------------------
__global__ __launch_bounds__(256) void pos_kernel(
    const float* __restrict__ x, const float* __restrict__ pw,
    const float* __restrict__ pb)
{
    int idx = blockIdx.x * 256 + threadIdx.x;
    if (idx >= B_*C_*P_) return;
    int pix = idx & (P_-1);
    int bc  = idx >> 14;          // P_ = 16384 = 2^14
    int c   = bc % C_;
    int y  = pix >> 7;            // W_ = 128
    int xx = pix & 127;
    const float* xb = x + (size_t)bc * P_;
    const float* w  = pw + c * 9;
    float s = x[idx];
    #pragma unroll
    for (int kh = 0; kh < 3; kh++) {
        int yy = y + kh - 1;
        if (yy < 0 || yy >= H_) continue;
        #pragma unroll
        for (int kw = 0; kw < 3; kw++) {
            int xc = xx + kw - 1;
            if (xc < 0 || xc >= W_) continue;
            s += xb[yy * W_ + xc] * w[kh * 3 + kw];
        }
    }
    g_x[idx] = s + pb[c];
}

// ---------------------------------------------------------------------------
// SGEMM: Y[b,m,p] = sum_c Wm[m,c] * X[b,c,p]   (K = C_ = 192)
// BM=64, BN=128, BK=16; 256 threads; 4x8 accum per thread.
// ---------------------------------------------------------------------------
#define BM 64
#define BN 128
#define BK 16

__global__ __launch_bounds__(256) void gemm_kernel(
    const float* __restrict__ Wm, const float* __restrict__ X,
    float* __restrict__ Y, int M)
{
    int b = blockIdx.z;
    const float* Xb = X + (size_t)b * C_ * P_;
    float* Yb = Y + (size_t)b * M * P_;

    __shared__ float As[BM][BK];     // [m][k] — coalesced fill along k
    __shared__ float Bs[BK][BN];

    int m0 = blockIdx.y * BM;
    int n0 = blockIdx.x * BN;
    int tid = threadIdx.x;
    int tx = tid & 15;       // n-tile group (8 cols)
    int ty = tid >> 4;       // m-tile group (4 rows)

    float acc[4][8];
    #pragma unroll
    for (int i = 0; i < 4; i++)
        #pragma unroll
        for (int j = 0; j < 8; j++) acc[i][j] = 0.f;

    for (int k0 = 0; k0 < C_; k0 += BK) {
        // A tile: 64x16 = 1024 elems, 4 per thread; k fastest -> coalesced
        #pragma unroll
        for (int i = tid; i < BM*BK; i += 256) {
            int m = i >> 4, k = i & 15;
            As[m][k] = Wm[(size_t)(m0 + m) * C_ + k0 + k];
        }
        // B tile: 16x128 = 2048 elems, 8 per thread; n fastest -> coalesced
        #pragma unroll
        for (int i = tid; i < BK*BN; i += 256) {
            int k = i >> 7, n = i & 127;
            Bs[k][n] = Xb[(size_t)(k0 + k) * P_ + n0 + n];
        }
        __syncthreads();
        #pragma unroll
        for (int k = 0; k < BK; k++) {
            float a[4], bb[8];
            #pragma unroll
            for (int i = 0; i < 4; i++) a[i] = As[ty*4 + i][k];
            #pragma unroll
            for (int j = 0; j < 8; j++) bb[j] = Bs[k][tx*8 + j];
            #pragma unroll
            for (int i = 0; i < 4; i++)
                #pragma unroll
                for (int j = 0; j < 8; j++)
                    acc[i][j] += a[i] * bb[j];
        }
        __syncthreads();
    }

    #pragma unroll
    for (int i = 0; i < 4; i++) {
        float* yr = Yb + (size_t)(m0 + ty*4 + i) * P_ + n0 + tx*8;
        #pragma unroll
        for (int j = 0; j < 8; j++) yr[j] = acc[i][j];
    }
}

// ---------------------------------------------------------------------------
// Stage 3: multi-dilate window attention.
// One thread per (pixel, head, dilation). 9 neighbors, reflect padding.
// ---------------------------------------------------------------------------
__device__ __forceinline__ int reflect_i(int t, int n) {
    return t < 0 ? -t : (t >= n ? 2*n - 2 - t : t);
}

__global__ __launch_bounds__(256) void attn_kernel()
{
    int p    = blockIdx.x * 256 + threadIdx.x;
    int head = blockIdx.y & 1;
    int dil  = blockIdx.y >> 1;      // 0,1,2
    int b    = blockIdx.z;
    int dl   = dil + 1;              // dilation value

    int y  = p >> 7;
    int xx = p & 127;

    int nb[9];
    #pragma unroll
    for (int jy = 0; jy < 3; jy++) {
        int yy = reflect_i(y + (jy-1)*dl, H_);
        #pragma unroll
        for (int jx = 0; jx < 3; jx++) {
            int xc = reflect_i(xx + (jx-1)*dl, W_);
            nb[jy*3 + jx] = yy * W_ + xc;
        }
    }

    size_t chan0 = (size_t)b * MQKV + dil * C2 + head * HD;
    const float* qp = g_qkv + chan0 * P_;                        // q channels
    const float* kp = g_qkv + (chan0 + (size_t)C_)   * P_;       // k channels
    const float* vp = g_qkv + (chan0 + (size_t)2*C_) * P_;       // v channels

    float sc[9];
    #pragma unroll
    for (int j = 0; j < 9; j++) sc[j] = 0.f;

    #pragma unroll 4
    for (int d = 0; d < HD; d++) {
        float qd = qp[(size_t)d * P_ + p];
        const float* kr = kp + (size_t)d * P_;
        #pragma unroll
        for (int j = 0; j < 9; j++) sc[j] += qd * kr[nb[j]];
    }

    // softmax over 9 (with max-subtraction, matching jax.nn.softmax)
    float mx = sc[0] * SCALE;
    #pragma unroll
    for (int j = 0; j < 9; j++) { sc[j] *= SCALE; mx = fmaxf(mx, sc[j]); }
    float sum = 0.f;
    #pragma unroll
    for (int j = 0; j < 9; j++) { sc[j] = __expf(sc[j] - mx); sum += sc[j]; }
    float inv = 1.f / sum;

    float* op = g_xo + ((size_t)b * C_ + dil * C2 + head * HD) * P_ + p;
    #pragma unroll 4
    for (int d = 0; d < HD; d++) {
        const float* vr = vp + (size_t)d * P_;
        float a = 0.f;
        #pragma unroll
        for (int j = 0; j < 9; j++) a += sc[j] * vr[nb[j]];
        op[(size_t)d * P_] = a * inv;
    }
}

// ---------------------------------------------------------------------------
extern "C" void kernel_launch(void* const* d_in, const int* in_sizes, int n_in,
                              void* d_out, int out_size)
{
    const float* x     = (const float*)d_in[0];
    const float* pos_w = (const float*)d_in[1];
    const float* pos_b = (const float*)d_in[2];
    const float* qkv_w = (const float*)d_in[3];
    const float* proj_w= (const float*)d_in[4];
    float* out = (float*)d_out;

    float *gx, *gq, *go;
    cudaGetSymbolAddress((void**)&gx, g_x);
    cudaGetSymbolAddress((void**)&gq, g_qkv);
    cudaGetSymbolAddress((void**)&go, g_xo);

    // Stage 1: positional dwconv + residual + bias
    {
        int total = B_*C_*P_;
        pos_kernel<<<(total + 255)/256, 256>>>(x, pos_w, pos_b);
    }
    // Stage 2: qkv 1x1 conv (GEMM 576 x 192 x 16384, per batch)
    {
        dim3 grid(P_/BN, MQKV/BM, B_);
        gemm_kernel<<<grid, 256>>>(qkv_w, gx, gq, MQKV);
    }
    // Stage 3: attention per dilation/head
    {
        dim3 grid(P_/256, NH*ND, B_);
        attn_kernel<<<grid, 256>>>();
    }
    // Stage 4: projection (GEMM 192 x 192 x 16384, per batch)
    {
        dim3 grid(P_/BN, C_/BM, B_);
        gemm_kernel<<<grid, 256>>>(proj_w, go, out, C_);
    }
}

// round 6
// speedup vs baseline: 2.7085x; 2.7085x over previous
#include <cuda_runtime.h>
#include <cstdint>
#include <cstddef>

// Problem constants
#define B_   4
#define C_   192
#define H_   128
#define W_   128
#define P_   16384
#define ND   3
#define C2   64
#define NH   2
#define HD   32
#define MQKV 576
#define SCALE 0.17677669529663687f   // 32^-0.5

// Scratch (alloc-free: __device__ globals)
__device__ float g_x  [(size_t)B_*C_*P_];
__device__ float g_qkv[(size_t)B_*MQKV*P_];
__device__ float g_xo [(size_t)B_*C_*P_];

// ---------------------------------------------------------------------------
// Stage 1: depthwise 3x3 conv (zero pad) + residual + bias
// ---------------------------------------------------------------------------
__global__ __launch_bounds__(256) void pos_kernel(
    const float* __restrict__ x, const float* __restrict__ pw,
    const float* __restrict__ pb)
{
    int idx = blockIdx.x * 256 + threadIdx.x;
    if (idx >= B_*C_*P_) return;
    int pix = idx & (P_-1);
    int bc  = idx >> 14;
    int c   = bc % C_;
    int y  = pix >> 7;
    int xx = pix & 127;
    const float* xb = x + (size_t)bc * P_;
    const float* w  = pw + c * 9;
    float s = x[idx];
    #pragma unroll
    for (int kh = 0; kh < 3; kh++) {
        int yy = y + kh - 1;
        if (yy < 0 || yy >= H_) continue;
        #pragma unroll
        for (int kw = 0; kw < 3; kw++) {
            int xc = xx + kw - 1;
            if (xc < 0 || xc >= W_) continue;
            s += xb[yy * W_ + xc] * w[kh * 3 + kw];
        }
    }
    g_x[idx] = s + pb[c];
}

// ---------------------------------------------------------------------------
// tf32 mma.sync GEMM:  Y[b, m, p] = sum_c Wm[m, c] * X[b, c, p]
// Block = one 128-pixel tile (n) for one batch. Full-K X tile (192 x 128)
// stays in SMEM across the internal m-loop (64 output channels per step),
// so X is read from DRAM exactly once per GEMM. W (<=442 KB) lives in L2.
// 8 warps: 2 (m) x 4 (n); warp tile 32x32 via m16n8k8 tf32 HMMA.
// ---------------------------------------------------------------------------
#define GBM 64
#define GBN 128
#define GK  192
#define KP  196            // A row pad (floats): bank = (4m + k) % 32, conflict-free
#define BNP 136            // B row pad (floats): bank = (8k + n) % 32, conflict-free
#define OP  132            // epilogue stage row pad
#define SM_AS_OFF (GK * BNP)                 // Bs first: 26112 floats
#define SM_FLOATS (SM_AS_OFF + GBM * KP)     // + As 12544 floats = 38656
#define SM_BYTES  (SM_FLOATS * 4)            // 154624 bytes

__device__ __forceinline__ float f2tf(float f) {
    uint32_t u;
    asm("cvt.rna.tf32.f32 %0, %1;" : "=r"(u) : "f"(f));
    return __uint_as_float(u);
}

__device__ __forceinline__ void mma_tf32(float (&d)[4], const uint32_t (&a)[4],
                                         const uint32_t (&b)[2]) {
    asm volatile(
        "mma.sync.aligned.m16n8k8.row.col.f32.tf32.tf32.f32 "
        "{%0,%1,%2,%3}, {%4,%5,%6,%7}, {%8,%9}, {%0,%1,%2,%3};"
        : "+f"(d[0]), "+f"(d[1]), "+f"(d[2]), "+f"(d[3])
        : "r"(a[0]), "r"(a[1]), "r"(a[2]), "r"(a[3]), "r"(b[0]), "r"(b[1]));
}

__global__ __launch_bounds__(256, 1) void gemm_mma(
    const float* __restrict__ Wm, const float* __restrict__ X,
    float* __restrict__ Y, int Mtot)
{
    extern __shared__ float sm[];
    float* Bs = sm;                 // [GK][BNP]
    float* As = sm + SM_AS_OFF;     // [GBM][KP]; reused as epilogue stage [GBM][OP]
    const uint32_t* Bsu = reinterpret_cast<const uint32_t*>(Bs);
    const uint32_t* Asu = reinterpret_cast<const uint32_t*>(As);

    int tid  = threadIdx.x;
    int lane = tid & 31;
    int wid  = tid >> 5;
    int wm   = wid & 1;             // 2 warps along m
    int wn   = wid >> 1;            // 4 warps along n
    int b    = blockIdx.y;
    int n0   = blockIdx.x * GBN;
    const float* Xb = X + (size_t)b * C_ * P_;
    float* Yb = Y + (size_t)b * Mtot * P_;

    // Fill Bs once: X[k][n0..n0+127], converted to tf32 bits. 6144 float4s.
    #pragma unroll
    for (int i = 0; i < 24; i++) {
        int idx = tid + i * 256;
        int row = idx >> 5;
        int c4  = (idx & 31) << 2;
        float4 v = *reinterpret_cast<const float4*>(Xb + (size_t)row * P_ + n0 + c4);
        float4 t;
        t.x = f2tf(v.x); t.y = f2tf(v.y); t.z = f2tf(v.z); t.w = f2tf(v.w);
        *reinterpret_cast<float4*>(Bs + row * BNP + c4) = t;
    }

    int lr = lane >> 2;   // 0..7
    int lc = lane & 3;    // 0..3

    for (int m0 = 0; m0 < Mtot; m0 += GBM) {
        __syncthreads();   // Bs ready (iter 0); prior epilogue stage consumed (iter >0)

        // Fill As: W[m0+r][0..191] as tf32 bits. 3072 float4s.
        #pragma unroll
        for (int i = 0; i < 12; i++) {
            int idx = tid + i * 256;
            int row = idx / 48;
            int c4  = (idx - row * 48) * 4;
            float4 v = *reinterpret_cast<const float4*>(Wm + (size_t)(m0 + row) * GK + c4);
            float4 t;
            t.x = f2tf(v.x); t.y = f2tf(v.y); t.z = f2tf(v.z); t.w = f2tf(v.w);
            *reinterpret_cast<float4*>(As + row * KP + c4) = t;
        }
        __syncthreads();

        float acc[2][4][4];
        #pragma unroll
        for (int mt = 0; mt < 2; mt++)
            #pragma unroll
            for (int nt = 0; nt < 4; nt++)
                #pragma unroll
                for (int r = 0; r < 4; r++) acc[mt][nt][r] = 0.f;

        #pragma unroll
        for (int ks = 0; ks < 24; ks++) {
            int k = ks * 8;
            uint32_t a[2][4], bf[4][2];
            #pragma unroll
            for (int mt = 0; mt < 2; mt++) {
                int r0 = (wm * 32 + mt * 16 + lr) * KP + k + lc;
                a[mt][0] = Asu[r0];
                a[mt][1] = Asu[r0 + 8 * KP];
                a[mt][2] = Asu[r0 + 4];
                a[mt][3] = Asu[r0 + 8 * KP + 4];
            }
            #pragma unroll
            for (int nt = 0; nt < 4; nt++) {
                int c0 = (k + lc) * BNP + wn * 32 + nt * 8 + lr;
                bf[nt][0] = Bsu[c0];
                bf[nt][1] = Bsu[c0 + 4 * BNP];
            }
            #pragma unroll
            for (int mt = 0; mt < 2; mt++)
                #pragma unroll
                for (int nt = 0; nt < 4; nt++)
                    mma_tf32(acc[mt][nt], a[mt], bf[nt]);
        }
        __syncthreads();   // all warps done reading As before staging over it

        // Stage fragments into As region as [64][OP] for coalesced stores
        float* Os = As;
        #pragma unroll
        for (int mt = 0; mt < 2; mt++)
            #pragma unroll
            for (int nt = 0; nt < 4; nt++) {
                int r = wm * 32 + mt * 16 + lr;
                int c = wn * 32 + nt * 8 + lc * 2;
                Os[r * OP + c]           = acc[mt][nt][0];
                Os[r * OP + c + 1]       = acc[mt][nt][1];
                Os[(r + 8) * OP + c]     = acc[mt][nt][2];
                Os[(r + 8) * OP + c + 1] = acc[mt][nt][3];
            }
        __syncthreads();

        // Coalesced write-out: 64 rows x 128 floats = 2048 float4s
        #pragma unroll
        for (int i = 0; i < 8; i++) {
            int idx = tid + i * 256;
            int row = idx >> 5;
            int c4  = (idx & 31) << 2;
            float4 v = *reinterpret_cast<const float4*>(Os + row * OP + c4);
            *reinterpret_cast<float4*>(Yb + (size_t)(m0 + row) * P_ + n0 + c4) = v;
        }
    }
}

// ---------------------------------------------------------------------------
// Stage 3: multi-dilate window attention
// ---------------------------------------------------------------------------
__device__ __forceinline__ int reflect_i(int t, int n) {
    return t < 0 ? -t : (t >= n ? 2*n - 2 - t : t);
}

__global__ __launch_bounds__(256) void attn_kernel()
{
    int p    = blockIdx.x * 256 + threadIdx.x;
    int head = blockIdx.y & 1;
    int dil  = blockIdx.y >> 1;
    int b    = blockIdx.z;
    int dl   = dil + 1;

    int y  = p >> 7;
    int xx = p & 127;

    int nb[9];
    #pragma unroll
    for (int jy = 0; jy < 3; jy++) {
        int yy = reflect_i(y + (jy-1)*dl, H_);
        #pragma unroll
        for (int jx = 0; jx < 3; jx++) {
            int xc = reflect_i(xx + (jx-1)*dl, W_);
            nb[jy*3 + jx] = yy * W_ + xc;
        }
    }

    size_t chan0 = (size_t)b * MQKV + dil * C2 + head * HD;
    const float* qp = g_qkv + chan0 * P_;
    const float* kp = g_qkv + (chan0 + (size_t)C_)   * P_;
    const float* vp = g_qkv + (chan0 + (size_t)2*C_) * P_;

    float sc[9];
    #pragma unroll
    for (int j = 0; j < 9; j++) sc[j] = 0.f;

    #pragma unroll 4
    for (int d = 0; d < HD; d++) {
        float qd = qp[(size_t)d * P_ + p];
        const float* kr = kp + (size_t)d * P_;
        #pragma unroll
        for (int j = 0; j < 9; j++) sc[j] += qd * kr[nb[j]];
    }

    float mx = sc[0] * SCALE;
    #pragma unroll
    for (int j = 0; j < 9; j++) { sc[j] *= SCALE; mx = fmaxf(mx, sc[j]); }
    float sum = 0.f;
    #pragma unroll
    for (int j = 0; j < 9; j++) { sc[j] = __expf(sc[j] - mx); sum += sc[j]; }
    float inv = 1.f / sum;

    float* op = g_xo + ((size_t)b * C_ + dil * C2 + head * HD) * P_ + p;
    #pragma unroll 4
    for (int d = 0; d < HD; d++) {
        const float* vr = vp + (size_t)d * P_;
        float a = 0.f;
        #pragma unroll
        for (int j = 0; j < 9; j++) a += sc[j] * vr[nb[j]];
        op[(size_t)d * P_] = a * inv;
    }
}

// ---------------------------------------------------------------------------
extern "C" void kernel_launch(void* const* d_in, const int* in_sizes, int n_in,
                              void* d_out, int out_size)
{
    const float* x      = (const float*)d_in[0];
    const float* pos_w  = (const float*)d_in[1];
    const float* pos_b  = (const float*)d_in[2];
    const float* qkv_w  = (const float*)d_in[3];
    const float* proj_w = (const float*)d_in[4];
    float* out = (float*)d_out;

    float *gx, *gq, *go;
    cudaGetSymbolAddress((void**)&gx, g_x);
    cudaGetSymbolAddress((void**)&gq, g_qkv);
    cudaGetSymbolAddress((void**)&go, g_xo);

    cudaFuncSetAttribute(gemm_mma, cudaFuncAttributeMaxDynamicSharedMemorySize, SM_BYTES);

    // Stage 1: positional dwconv + residual + bias
    {
        int total = B_*C_*P_;
        pos_kernel<<<(total + 255)/256, 256>>>(x, pos_w, pos_b);
    }
    // Stage 2: qkv 1x1 conv (576 x 192 x 16384 per batch)
    {
        dim3 grid(P_/GBN, B_);
        gemm_mma<<<grid, 256, SM_BYTES>>>(qkv_w, gx, gq, MQKV);
    }
    // Stage 3: attention
    {
        dim3 grid(P_/256, NH*ND, B_);
        attn_kernel<<<grid, 256>>>();
    }
    // Stage 4: projection (192 x 192 x 16384 per batch)
    {
        dim3 grid(P_/GBN, B_);
        gemm_mma<<<grid, 256, SM_BYTES>>>(proj_w, go, out, C_);
    }
}